// round 3
// baseline (speedup 1.0000x reference)
#include <cuda_runtime.h>

#define W_      10
#define NSTATE  4096
#define BATCH   512
#define NIN     6
#define STAGES  2

// g_tab[(s*W + out)*1024 + g] = (cos(phi/2), sin(phi/2)),
// phi = theta_bias + sum_i bit_i(g)*theta_i, g = state bits 11..2 (bit (9-i) <-> lane i)
__device__ float2 g_tab[STAGES * W_ * 1024];
__device__ float2 u_tab[STAGES * W_];

__global__ void precompute_kernel(const float* __restrict__ unitary_theta,
                                  const float* __restrict__ neuron_theta) {
    int idx = blockIdx.x * blockDim.x + threadIdx.x;
    if (idx < STAGES * W_ * 1024) {
        int g  = idx & 1023;
        int sn = idx >> 10;
        const float* th = neuron_theta + sn * (W_ + 1);
        float phi = th[W_];
        #pragma unroll
        for (int i = 0; i < W_; i++)
            if ((g >> (9 - i)) & 1) phi += th[i];
        float sv, cv;
        sincosf(phi * 0.5f, &sv, &cv);
        g_tab[idx] = make_float2(cv, sv);
    }
    if (idx < STAGES * W_) {
        float sv, cv;
        sincosf(unitary_theta[idx] * 0.5f, &sv, &cv);
        u_tab[idx] = make_float2(cv, sv);
    }
}

// Group transform: RY(+phi) on q10, CRY(sgn*pi) 10->11, RY(-phi) on q10,
// acting on 4 contiguous amps (bit1=q10, bit0=q11).
__device__ __forceinline__ void grp4(float4& a, float c, float s, float sgn) {
    float t0 = c * a.x - s * a.z;
    float t1 = c * a.y - s * a.w;
    float t2 = s * a.x + c * a.z;
    float t3 = s * a.y + c * a.w;
    float u2 = -sgn * t3, u3 = sgn * t2;
    a.x =  c * t0 + s * u2;
    a.y =  c * t1 + s * u3;
    a.z = -s * t0 + c * u2;
    a.w = -s * t1 + c * u3;
}

// Full neuron on 8 amps: A0 = target-bit=0 groups, A1 = target-bit=1.
__device__ __forceinline__ void neuron8(float4& A0, float4& A1, float2 cs0, float2 cs1) {
    grp4(A0, cs0.x, cs0.y, 1.f);
    grp4(A1, cs1.x, cs1.y, 1.f);
    // pass B: CRY(pi, q11 -> target bit): offsets l=1,3 (q11=1)
    float x1 = A0.y; A0.y = -A1.y; A1.y = x1;
    float x3 = A0.w; A0.w = -A1.w; A1.w = x3;
    grp4(A0, cs0.x, cs0.y, -1.f);
    grp4(A1, cs1.x, cs1.y, -1.f);
}

// RY on bit b of a 16-element register array (pairs (k, k+2^b), bit b of k == 0)
__device__ __forceinline__ void ry16(float r[16], int b, float2 cs) {
    #pragma unroll
    for (int k = 0; k < 16; k++) {
        if (!((k >> b) & 1)) {
            int k1 = k | (1 << b);
            float a0 = r[k], a1 = r[k1];
            r[k]  = cs.x * a0 - cs.y * a1;
            r[k1] = cs.y * a0 + cs.x * a1;
        }
    }
}

__device__ __forceinline__ void ry4pair(float4& a, float4& b, float2 cs) {
    float4 na, nb;
    na.x = cs.x * a.x - cs.y * b.x;  nb.x = cs.y * a.x + cs.x * b.x;
    na.y = cs.x * a.y - cs.y * b.y;  nb.y = cs.y * a.y + cs.x * b.y;
    na.z = cs.x * a.z - cs.y * b.z;  nb.z = cs.y * a.z + cs.x * b.z;
    na.w = cs.x * a.w - cs.y * b.w;  nb.w = cs.y * a.w + cs.x * b.w;
    a = na; b = nb;
}

// Neuron-pair sweep: neurons oA = 11-PA (target bit PA) then oA+1 (bit PA-1).
// Item owns bits {PA, PA-1, 1, 0} = 16 amps (4 float4 groups).
template <int PA>
__device__ __forceinline__ void neuron_pair(float* st,
                                            const float2* __restrict__ tabA,
                                            const float2* __restrict__ tabB,
                                            int t) {
    constexpr int PB = PA - 1;
    constexpr int LB = PB - 2;            // low free bits of group index
    float4* st4 = (float4*)st;
    const int low  = t & ((1 << LB) - 1);
    const int high = t >> LB;
    const int gb   = low | (high << (PA - 1));

    const int g00 = gb;
    const int g01 = gb + (1 << (PB - 2));
    const int g10 = gb + (1 << (PA - 2));
    const int g11 = g10 + (1 << (PB - 2));

    float4 q00 = st4[g00], q01 = st4[g01], q10 = st4[g10], q11 = st4[g11];

    // neuron oA: target dim j
    neuron8(q00, q10, tabA[g00], tabA[g10]);
    neuron8(q01, q11, tabA[g01], tabA[g11]);
    // neuron oA+1: target dim i
    neuron8(q00, q01, tabB[g00], tabB[g01]);
    neuron8(q10, q11, tabB[g10], tabB[g11]);

    st4[g00] = q00; st4[g01] = q01; st4[g10] = q10; st4[g11] = q11;
}

__global__ void __launch_bounds__(256, 4) sim_kernel(
    const float* __restrict__ psi_in,
    const int*   __restrict__ inp,
    float*       __restrict__ probs_out,
    float*       __restrict__ psi_out)
{
    __shared__ float st[NSTATE];
    __shared__ float red[256];

    const int b   = blockIdx.x;
    const int tid = threadIdx.x;

    int mask = 0;
    #pragma unroll
    for (int l = 0; l < NIN; l++) mask |= (inp[l] & 1) << (11 - l);

    #pragma unroll
    for (int s = 0; s < STAGES; s++) {
        const float2* ut = &u_tab[s * W_];

        // ---- P1: unitary lanes 0-3 (bits 11..8). amps = tid + k*256.
        {
            float r[16];
            if (s == 0) {
                const float* in = psi_in + (size_t)b * NSTATE;
                #pragma unroll
                for (int k = 0; k < 16; k++) r[k] = in[(tid + (k << 8)) ^ mask];
            } else {
                #pragma unroll
                for (int k = 0; k < 16; k++) r[k] = st[tid + (k << 8)];
            }
            ry16(r, 3, ut[0]); ry16(r, 2, ut[1]); ry16(r, 1, ut[2]); ry16(r, 0, ut[3]);
            #pragma unroll
            for (int k = 0; k < 16; k++) st[tid + (k << 8)] = r[k];
        }
        __syncthreads();

        // ---- P2: unitary lanes 4-7 (bits 7..4). amps = base + k*16.
        {
            const int base = (tid & 15) | ((tid >> 4) << 8);
            float r[16];
            #pragma unroll
            for (int k = 0; k < 16; k++) r[k] = st[base + (k << 4)];
            ry16(r, 3, ut[4]); ry16(r, 2, ut[5]); ry16(r, 1, ut[6]); ry16(r, 0, ut[7]);
            #pragma unroll
            for (int k = 0; k < 16; k++) st[base + (k << 4)] = r[k];
        }
        __syncthreads();

        // ---- P3: unitary lanes 8,9 (bits 3,2). 16 contiguous amps.
        {
            float4* st4 = (float4*)st;
            float4 v0 = st4[(tid << 2) + 0];
            float4 v1 = st4[(tid << 2) + 1];
            float4 v2 = st4[(tid << 2) + 2];
            float4 v3 = st4[(tid << 2) + 3];
            ry4pair(v0, v2, ut[8]);  ry4pair(v1, v3, ut[8]);   // bit 3 (lane 8)
            ry4pair(v0, v1, ut[9]);  ry4pair(v2, v3, ut[9]);   // bit 2 (lane 9)
            st4[(tid << 2) + 0] = v0;
            st4[(tid << 2) + 1] = v1;
            st4[(tid << 2) + 2] = v2;
            st4[(tid << 2) + 3] = v3;
        }
        __syncthreads();

        // ---- P4..P7: neuron pairs (0,1),(2,3),(4,5),(6,7)
        const float2* tb = &g_tab[(s * W_) << 10];
        neuron_pair<11>(st, tb + (0 << 10), tb + (1 << 10), tid); __syncthreads();
        neuron_pair<9 >(st, tb + (2 << 10), tb + (3 << 10), tid); __syncthreads();
        neuron_pair<7 >(st, tb + (4 << 10), tb + (5 << 10), tid); __syncthreads();
        neuron_pair<5 >(st, tb + (6 << 10), tb + (7 << 10), tid); __syncthreads();

        // ---- P8: neurons 8,9 (bits 3,2). Group idx == float4 idx == (tid<<2)+2j+i.
        {
            const float2* tabA = tb + (8 << 10);
            const float2* tabB = tb + (9 << 10);
            float4* st4 = (float4*)st;
            const int g0 = tid << 2;
            float4 q00 = st4[g0], q01 = st4[g0 + 1], q10 = st4[g0 + 2], q11 = st4[g0 + 3];

            neuron8(q00, q10, tabA[g0],     tabA[g0 + 2]);
            neuron8(q01, q11, tabA[g0 + 1], tabA[g0 + 3]);
            neuron8(q00, q01, tabB[g0],     tabB[g0 + 1]);
            neuron8(q10, q11, tabB[g0 + 2], tabB[g0 + 3]);

            if (s == STAGES - 1) {
                float4* out4 = (float4*)(psi_out + (size_t)b * NSTATE);
                out4[g0] = q00; out4[g0 + 1] = q01; out4[g0 + 2] = q10; out4[g0 + 3] = q11;
                float ssq =
                    q00.x*q00.x + q00.y*q00.y + q00.z*q00.z + q00.w*q00.w +
                    q01.x*q01.x + q01.y*q01.y + q01.z*q01.z + q01.w*q01.w +
                    q10.x*q10.x + q10.y*q10.y + q10.z*q10.z + q10.w*q10.w +
                    q11.x*q11.x + q11.y*q11.y + q11.z*q11.z + q11.w*q11.w;
                red[tid] = ssq;
            } else {
                st4[g0] = q00; st4[g0 + 1] = q01; st4[g0 + 2] = q10; st4[g0 + 3] = q11;
            }
        }
        __syncthreads();
    }

    // ---- probs: bucket = bits 11..6 = tid>>2 of the 16-amp items
    if (tid < 64) {
        probs_out[b * 64 + tid] =
            red[4 * tid] + red[4 * tid + 1] + red[4 * tid + 2] + red[4 * tid + 3];
    }
}

extern "C" void kernel_launch(void* const* d_in, const int* in_sizes, int n_in,
                              void* d_out, int out_size) {
    const float* psi = (const float*)d_in[0];
    const int*   inp = (const int*)d_in[1];
    const float* uth = (const float*)d_in[2];
    const float* nth = (const float*)d_in[3];
    float* out = (float*)d_out;

    float* probs_out = out;
    float* psi_out   = out + BATCH * 64;

    precompute_kernel<<<(STAGES * W_ * 1024 + 255) / 256, 256>>>(uth, nth);
    sim_kernel<<<BATCH, 256>>>(psi, inp, probs_out, psi_out);
}

// round 4
// speedup vs baseline: 1.0534x; 1.0534x over previous
#include <cuda_runtime.h>

#define W_      10
#define NSTATE  4096
#define BATCH   512
#define NIN     6
#define STAGES  2

// g_tab[(s*W + out)*1024 + g] = (cos(phi/2), sin(phi/2)),
// phi = theta_bias + sum_i bit_i(g)*theta_i, g = state bits 11..2 (bit (9-i) <-> lane i)
__device__ float2 g_tab[STAGES * W_ * 1024];
__device__ float2 u_tab[STAGES * W_];

__global__ void precompute_kernel(const float* __restrict__ unitary_theta,
                                  const float* __restrict__ neuron_theta) {
    int idx = blockIdx.x * blockDim.x + threadIdx.x;
    if (idx < STAGES * W_ * 1024) {
        int g  = idx & 1023;
        int sn = idx >> 10;
        const float* th = neuron_theta + sn * (W_ + 1);
        float phi = th[W_];
        #pragma unroll
        for (int i = 0; i < W_; i++)
            if ((g >> (9 - i)) & 1) phi += th[i];
        float sv, cv;
        sincosf(phi * 0.5f, &sv, &cv);
        g_tab[idx] = make_float2(cv, sv);
    }
    if (idx < STAGES * W_) {
        float sv, cv;
        sincosf(unitary_theta[idx] * 0.5f, &sv, &cv);
        u_tab[idx] = make_float2(cv, sv);
    }
}

// ---- smem anti-bank-conflict swizzle (bijection on the float4 index).
// low2 bits <- g bits {3,4}; bit2 <- g4 ^ g6. Makes every sweep's lane->bank
// map conflict-free per 8-lane phase.
__device__ __forceinline__ int sw4(int g) {
    return g ^ (((g >> 3) & 3) | (((g >> 2) ^ (g >> 4)) & 4));
}
__device__ __forceinline__ int swf(int i) {
    return (sw4(i >> 2) << 2) | (i & 3);
}

// Group transform: RY(+phi) on q10, CRY(sgn*pi) 10->11, RY(-phi) on q10,
// acting on 4 contiguous amps (bit1=q10, bit0=q11).
__device__ __forceinline__ void grp4(float4& a, float c, float s, float sgn) {
    float t0 = c * a.x - s * a.z;
    float t1 = c * a.y - s * a.w;
    float t2 = s * a.x + c * a.z;
    float t3 = s * a.y + c * a.w;
    float u2 = -sgn * t3, u3 = sgn * t2;
    a.x =  c * t0 + s * u2;
    a.y =  c * t1 + s * u3;
    a.z = -s * t0 + c * u2;
    a.w = -s * t1 + c * u3;
}

// Full neuron on 8 amps: A0 = target-bit=0 groups, A1 = target-bit=1.
__device__ __forceinline__ void neuron8(float4& A0, float4& A1, float2 cs0, float2 cs1) {
    grp4(A0, cs0.x, cs0.y, 1.f);
    grp4(A1, cs1.x, cs1.y, 1.f);
    float x1 = A0.y; A0.y = -A1.y; A1.y = x1;
    float x3 = A0.w; A0.w = -A1.w; A1.w = x3;
    grp4(A0, cs0.x, cs0.y, -1.f);
    grp4(A1, cs1.x, cs1.y, -1.f);
}

// RY on bit b of a 16-element register array
__device__ __forceinline__ void ry16(float r[16], int b, float2 cs) {
    #pragma unroll
    for (int k = 0; k < 16; k++) {
        if (!((k >> b) & 1)) {
            int k1 = k | (1 << b);
            float a0 = r[k], a1 = r[k1];
            r[k]  = cs.x * a0 - cs.y * a1;
            r[k1] = cs.y * a0 + cs.x * a1;
        }
    }
}

__device__ __forceinline__ void ry4pair(float4& a, float4& b, float2 cs) {
    float4 na, nb;
    na.x = cs.x * a.x - cs.y * b.x;  nb.x = cs.y * a.x + cs.x * b.x;
    na.y = cs.x * a.y - cs.y * b.y;  nb.y = cs.y * a.y + cs.x * b.y;
    na.z = cs.x * a.z - cs.y * b.z;  nb.z = cs.y * a.z + cs.x * b.z;
    na.w = cs.x * a.w - cs.y * b.w;  nb.w = cs.y * a.w + cs.x * b.w;
    a = na; b = nb;
}

// Neuron-pair sweep: neurons oA = 11-PA (target bit PA) then oA+1 (bit PA-1).
// Item owns bits {PA, PA-1, 1, 0} = 16 amps (4 float4 groups).
template <int PA>
__device__ __forceinline__ void neuron_pair(float* st,
                                            const float2* __restrict__ tabA,
                                            const float2* __restrict__ tabB,
                                            int t) {
    constexpr int PB = PA - 1;
    constexpr int LB = PB - 2;
    float4* st4 = (float4*)st;
    const int low  = t & ((1 << LB) - 1);
    const int high = t >> LB;
    const int gb   = low | (high << (PA - 1));

    const int g00 = gb;
    const int g01 = gb + (1 << (PB - 2));
    const int g10 = gb + (1 << (PA - 2));
    const int g11 = g10 + (1 << (PB - 2));

    float4 q00 = st4[sw4(g00)], q01 = st4[sw4(g01)];
    float4 q10 = st4[sw4(g10)], q11 = st4[sw4(g11)];

    neuron8(q00, q10, tabA[g00], tabA[g10]);
    neuron8(q01, q11, tabA[g01], tabA[g11]);
    neuron8(q00, q01, tabB[g00], tabB[g01]);
    neuron8(q10, q11, tabB[g10], tabB[g11]);

    st4[sw4(g00)] = q00; st4[sw4(g01)] = q01;
    st4[sw4(g10)] = q10; st4[sw4(g11)] = q11;
}

__global__ void __launch_bounds__(256, 4) sim_kernel(
    const float* __restrict__ psi_in,
    const int*   __restrict__ inp,
    float*       __restrict__ probs_out,
    float*       __restrict__ psi_out)
{
    __shared__ float st[NSTATE];
    __shared__ float red[256];

    const int b   = blockIdx.x;
    const int tid = threadIdx.x;

    int mask = 0;
    #pragma unroll
    for (int l = 0; l < NIN; l++) mask |= (inp[l] & 1) << (11 - l);

    #pragma unroll
    for (int s = 0; s < STAGES; s++) {
        const float2* ut = &u_tab[s * W_];

        // ---- P1: unitary lanes 0-3 (bits 11..8). amps = tid + k*256.
        {
            float r[16];
            if (s == 0) {
                const float* in = psi_in + (size_t)b * NSTATE;
                #pragma unroll
                for (int k = 0; k < 16; k++) r[k] = in[(tid + (k << 8)) ^ mask];
            } else {
                #pragma unroll
                for (int k = 0; k < 16; k++) r[k] = st[swf(tid + (k << 8))];
            }
            ry16(r, 3, ut[0]); ry16(r, 2, ut[1]); ry16(r, 1, ut[2]); ry16(r, 0, ut[3]);
            #pragma unroll
            for (int k = 0; k < 16; k++) st[swf(tid + (k << 8))] = r[k];
        }
        __syncthreads();

        // ---- P2: unitary lanes 4-7 (bits 7..4). amps = base + k*16.
        {
            const int base = (tid & 15) | ((tid >> 4) << 8);
            float r[16];
            #pragma unroll
            for (int k = 0; k < 16; k++) r[k] = st[swf(base + (k << 4))];
            ry16(r, 3, ut[4]); ry16(r, 2, ut[5]); ry16(r, 1, ut[6]); ry16(r, 0, ut[7]);
            #pragma unroll
            for (int k = 0; k < 16; k++) st[swf(base + (k << 4))] = r[k];
        }
        __syncthreads();

        // ---- P3: unitary lanes 8,9 (bits 3,2). 16 contiguous amps.
        {
            float4* st4 = (float4*)st;
            float4 v0 = st4[sw4((tid << 2) + 0)];
            float4 v1 = st4[sw4((tid << 2) + 1)];
            float4 v2 = st4[sw4((tid << 2) + 2)];
            float4 v3 = st4[sw4((tid << 2) + 3)];
            ry4pair(v0, v2, ut[8]);  ry4pair(v1, v3, ut[8]);
            ry4pair(v0, v1, ut[9]);  ry4pair(v2, v3, ut[9]);
            st4[sw4((tid << 2) + 0)] = v0;
            st4[sw4((tid << 2) + 1)] = v1;
            st4[sw4((tid << 2) + 2)] = v2;
            st4[sw4((tid << 2) + 3)] = v3;
        }
        __syncthreads();

        // ---- P4..P7: neuron pairs (0,1),(2,3),(4,5),(6,7)
        const float2* tb = &g_tab[(s * W_) << 10];
        neuron_pair<11>(st, tb + (0 << 10), tb + (1 << 10), tid); __syncthreads();
        neuron_pair<9 >(st, tb + (2 << 10), tb + (3 << 10), tid); __syncthreads();
        neuron_pair<7 >(st, tb + (4 << 10), tb + (5 << 10), tid); __syncthreads();
        neuron_pair<5 >(st, tb + (6 << 10), tb + (7 << 10), tid); __syncthreads();

        // ---- P8: neurons 8,9 (bits 3,2).
        {
            const float2* tabA = tb + (8 << 10);
            const float2* tabB = tb + (9 << 10);
            float4* st4 = (float4*)st;
            const int g0 = tid << 2;
            float4 q00 = st4[sw4(g0)],     q01 = st4[sw4(g0 + 1)];
            float4 q10 = st4[sw4(g0 + 2)], q11 = st4[sw4(g0 + 3)];

            neuron8(q00, q10, tabA[g0],     tabA[g0 + 2]);
            neuron8(q01, q11, tabA[g0 + 1], tabA[g0 + 3]);
            neuron8(q00, q01, tabB[g0],     tabB[g0 + 1]);
            neuron8(q10, q11, tabB[g0 + 2], tabB[g0 + 3]);

            if (s == STAGES - 1) {
                float4* out4 = (float4*)(psi_out + (size_t)b * NSTATE);
                out4[g0] = q00; out4[g0 + 1] = q01; out4[g0 + 2] = q10; out4[g0 + 3] = q11;
                float ssq =
                    q00.x*q00.x + q00.y*q00.y + q00.z*q00.z + q00.w*q00.w +
                    q01.x*q01.x + q01.y*q01.y + q01.z*q01.z + q01.w*q01.w +
                    q10.x*q10.x + q10.y*q10.y + q10.z*q10.z + q10.w*q10.w +
                    q11.x*q11.x + q11.y*q11.y + q11.z*q11.z + q11.w*q11.w;
                red[tid] = ssq;
            } else {
                st4[sw4(g0)] = q00;     st4[sw4(g0 + 1)] = q01;
                st4[sw4(g0 + 2)] = q10; st4[sw4(g0 + 3)] = q11;
            }
        }
        __syncthreads();
    }

    if (tid < 64) {
        probs_out[b * 64 + tid] =
            red[4 * tid] + red[4 * tid + 1] + red[4 * tid + 2] + red[4 * tid + 3];
    }
}

extern "C" void kernel_launch(void* const* d_in, const int* in_sizes, int n_in,
                              void* d_out, int out_size) {
    const float* psi = (const float*)d_in[0];
    const int*   inp = (const int*)d_in[1];
    const float* uth = (const float*)d_in[2];
    const float* nth = (const float*)d_in[3];
    float* out = (float*)d_out;

    float* probs_out = out;
    float* psi_out   = out + BATCH * 64;

    precompute_kernel<<<(STAGES * W_ * 1024 + 255) / 256, 256>>>(uth, nth);
    sim_kernel<<<BATCH, 256>>>(psi, inp, probs_out, psi_out);
}